// round 7
// baseline (speedup 1.0000x reference)
#include <cuda_runtime.h>
#include <cuda_fp16.h>
#include <cstdint>
#include <cstddef>

#define NB     4
#define NSEQ   4096
#define EDIM   128
#define FFD    512
#define NTOK   (NB * NSEQ)

// ---------------- scratch ----------------
__device__ float  g_h   [NTOK * EDIM];
__device__ float  g_S   [NTOK * EDIM];
__device__ __half g_Xh  [NTOK * 256];     // [t][256]: 2e=exp(k)*v, 2e+1=exp(k)
__device__ float  g_att [NTOK * EDIM];
__device__ float  g_out1[NTOK * EDIM];
__device__ float  g_h2  [NTOK * EDIM];
__device__ float  g_t   [NTOK * FFD];

// ---------------- helpers ----------------
__device__ __forceinline__ float tf32r(float x) {
    uint32_t u;
    asm("cvt.rna.tf32.f32 %0, %1;" : "=r"(u) : "f"(x));
    return __uint_as_float(u);
}
__device__ __forceinline__ void mma_tf32(float* c, const float* a, const float* b) {
    asm volatile(
        "mma.sync.aligned.m16n8k8.row.col.f32.tf32.tf32.f32 "
        "{%0,%1,%2,%3}, {%4,%5,%6,%7}, {%8,%9}, {%0,%1,%2,%3};\n"
        : "+f"(c[0]), "+f"(c[1]), "+f"(c[2]), "+f"(c[3])
        : "r"(__float_as_uint(a[0])), "r"(__float_as_uint(a[1])),
          "r"(__float_as_uint(a[2])), "r"(__float_as_uint(a[3])),
          "r"(__float_as_uint(b[0])), "r"(__float_as_uint(b[1])));
}
__device__ __forceinline__ void mma_f16(float* c, const uint32_t* a, const uint32_t* b) {
    asm volatile(
        "mma.sync.aligned.m16n8k16.row.col.f32.f16.f16.f32 "
        "{%0,%1,%2,%3}, {%4,%5,%6,%7}, {%8,%9}, {%0,%1,%2,%3};\n"
        : "+f"(c[0]), "+f"(c[1]), "+f"(c[2]), "+f"(c[3])
        : "r"(a[0]), "r"(a[1]), "r"(a[2]), "r"(a[3]), "r"(b[0]), "r"(b[1]));
}
__device__ __forceinline__ void cp16(void* s, const void* gp) {
    uint32_t sa = (uint32_t)__cvta_generic_to_shared(s);
    asm volatile("cp.async.cg.shared.global [%0], [%1], 16;\n" :: "r"(sa), "l"(gp));
}
__device__ __forceinline__ void cp_commit() {
    asm volatile("cp.async.commit_group;\n" ::: "memory");
}
__device__ __forceinline__ void cp_wait1() {
    asm volatile("cp.async.wait_group 1;\n" ::: "memory");
}
__device__ __forceinline__ void ldmx4(uint32_t& r0, uint32_t& r1, uint32_t& r2,
                                      uint32_t& r3, uint32_t addr) {
    asm volatile("ldmatrix.sync.aligned.m8n8.x4.shared.b16 {%0,%1,%2,%3}, [%4];"
                 : "=r"(r0), "=r"(r1), "=r"(r2), "=r"(r3) : "r"(addr));
}
__device__ __forceinline__ void ldmx4t(uint32_t& r0, uint32_t& r1, uint32_t& r2,
                                       uint32_t& r3, uint32_t addr) {
    asm volatile("ldmatrix.sync.aligned.m8n8.x4.trans.shared.b16 {%0,%1,%2,%3}, [%4];"
                 : "=r"(r0), "=r"(r1), "=r"(r2), "=r"(r3) : "r"(addr));
}
__device__ __forceinline__ uint32_t smem_u32(const void* p) {
    return (uint32_t)__cvta_generic_to_shared(p);
}

// ---------------- rmsnorm ----------------
__global__ void rmsnorm_kernel(const float* __restrict__ x,
                               const float* __restrict__ gw,
                               float* __restrict__ y) {
    int warp = (blockIdx.x * blockDim.x + threadIdx.x) >> 5;
    int lane = threadIdx.x & 31;
    if (warp >= NTOK) return;
    float4 v = reinterpret_cast<const float4*>(x + (size_t)warp * EDIM)[lane];
    float ss = v.x * v.x + v.y * v.y + v.z * v.z + v.w * v.w;
    #pragma unroll
    for (int o = 16; o > 0; o >>= 1) ss += __shfl_xor_sync(0xffffffffu, ss, o);
    float s = rsqrtf(ss * (1.0f / 128.0f) + 1e-6f);
    float4 g4 = reinterpret_cast<const float4*>(gw)[lane];
    float4 o4 = make_float4(v.x * s * g4.x, v.y * s * g4.y, v.z * s * g4.z, v.w * s * g4.w);
    reinterpret_cast<float4*>(y + (size_t)warp * EDIM)[lane] = o4;
}

// ---------------------------------------------------------------------------
// Fused QKV GEMM: one block = 128 tokens x 32 cols of q,k,v simultaneously.
// Epilogue: g_S = sigmoid(q); g_Xh[t][2e,2e+1] = half(exp(k)*v), half(exp(k)).
// ---------------------------------------------------------------------------
__global__ __launch_bounds__(256)
void qkv_kernel(const float* __restrict__ h, const float* __restrict__ Wq,
                const float* __restrict__ Wk, const float* __restrict__ Wv) {
    __shared__ float As[128 * 36];
    __shared__ float Bs[3][32 * 36];
    const int m0 = blockIdx.x * 128;
    const int j0 = blockIdx.y * 32;
    const int tid = threadIdx.x, lane = tid & 31, warp = tid >> 5;
    const int wm = warp >> 1, wn = warp & 1;    // 4 x 2 warps, 32m x 16n each
    const int g = lane >> 2, tg = lane & 3;

    float acc[3][2][2][4];
    #pragma unroll
    for (int w = 0; w < 3; w++)
        #pragma unroll
        for (int i = 0; i < 2; i++)
            #pragma unroll
            for (int j = 0; j < 2; j++)
                #pragma unroll
                for (int r = 0; r < 4; r++) acc[w][i][j][r] = 0.0f;

    const float* Wp[3] = {Wq, Wk, Wv};

    for (int k0 = 0; k0 < 128; k0 += 32) {
        #pragma unroll
        for (int i = 0; i < 4; i++) {
            int id = tid + i * 256;
            int m = id >> 3, c = (id & 7) << 2;
            float4 v = *reinterpret_cast<const float4*>(h + (size_t)(m0 + m) * 128 + k0 + c);
            float* p = As + m * 36 + c;
            p[0] = tf32r(v.x); p[1] = tf32r(v.y); p[2] = tf32r(v.z); p[3] = tf32r(v.w);
        }
        {
            int k = tid >> 3, c = (tid & 7) << 2;
            #pragma unroll
            for (int w = 0; w < 3; w++) {
                float4 v = *reinterpret_cast<const float4*>(Wp[w] + (size_t)(k0 + k) * 128 + j0 + c);
                float* p = Bs[w] + k * 36 + c;
                p[0] = tf32r(v.x); p[1] = tf32r(v.y); p[2] = tf32r(v.z); p[3] = tf32r(v.w);
            }
        }
        __syncthreads();
        #pragma unroll
        for (int ks = 0; ks < 4; ++ks) {
            const int kr = ks * 8 + tg;
            float a[2][4];
            #pragma unroll
            for (int mt = 0; mt < 2; ++mt) {
                int m = wm * 32 + mt * 16 + g;
                a[mt][0] = As[m * 36 + kr];
                a[mt][1] = As[(m + 8) * 36 + kr];
                a[mt][2] = As[m * 36 + kr + 4];
                a[mt][3] = As[(m + 8) * 36 + kr + 4];
            }
            #pragma unroll
            for (int w = 0; w < 3; w++) {
                #pragma unroll
                for (int nt = 0; nt < 2; ++nt) {
                    int n = wn * 16 + nt * 8 + g;
                    float bb[2];
                    bb[0] = Bs[w][kr * 36 + n];
                    bb[1] = Bs[w][(kr + 4) * 36 + n];
                    mma_tf32(acc[w][0][nt], a[0], bb);
                    mma_tf32(acc[w][1][nt], a[1], bb);
                }
            }
        }
        __syncthreads();
    }

    // epilogue
    #pragma unroll
    for (int mt = 0; mt < 2; ++mt) {
        #pragma unroll
        for (int nt = 0; nt < 2; ++nt) {
            const int col = j0 + wn * 16 + nt * 8 + tg * 2;
            #pragma unroll
            for (int hh = 0; hh < 2; ++hh) {
                const int row = m0 + wm * 32 + mt * 16 + g + hh * 8;
                float q0 = acc[0][mt][nt][hh * 2], q1 = acc[0][mt][nt][hh * 2 + 1];
                float k0v = acc[1][mt][nt][hh * 2], k1v = acc[1][mt][nt][hh * 2 + 1];
                float v0 = acc[2][mt][nt][hh * 2], v1 = acc[2][mt][nt][hh * 2 + 1];
                float2 s2 = make_float2(1.0f / (1.0f + expf(-q0)),
                                        1.0f / (1.0f + expf(-q1)));
                *reinterpret_cast<float2*>(g_S + (size_t)row * 128 + col) = s2;
                float kw0 = expf(k0v), kw1 = expf(k1v);
                __half2 h0 = __floats2half2_rn(kw0 * v0, kw0);
                __half2 h1 = __floats2half2_rn(kw1 * v1, kw1);
                uint2 u;
                u.x = *reinterpret_cast<uint32_t*>(&h0);
                u.y = *reinterpret_cast<uint32_t*>(&h1);
                *reinterpret_cast<uint2*>(g_Xh + (size_t)row * 256 + 2 * col) = u;
            }
        }
    }
}

// ---------------------------------------------------------------------------
// Big GEMM (fp16 m16n8k16), per batch: D[j,n] = sum_i exp(-coef*dis[i,j])*Xh[i,n]
// ---------------------------------------------------------------------------
#define AH_STR 40
#define AH_BUF 5120
#define BH_STR 264
#define BH_BUF 8448
#define BH_OFF 10240
#define BIG_SMEM 71168

__global__ __launch_bounds__(512, 1)
void big_kernel(const float* __restrict__ dis, const float* __restrict__ alphap) {
    extern __shared__ __half smh[];
    __half* Ah = smh;
    __half* Bh = smh + BH_OFF;
    const uint32_t smb = smem_u32(smh);

    const int tid = threadIdx.x, lane = tid & 31, warp = tid >> 5;
    const int wm = warp >> 2, wn = warp & 3;
    const int g = lane >> 2, tg = lane & 3;
    const int b = blockIdx.y, j0 = blockIdx.x * 128;
    const float coef = 12.0f * alphap[0];
    const float* Ag = dis + (size_t)b * NSEQ * NSEQ;
    const __half* Xg = g_Xh + (size_t)b * NSEQ * 256;

    const int am = tid & 127, ar4 = (tid >> 7) << 2;

    const int lr = lane & 7, sel = lane >> 3;
    uint32_t aoff[2];
    #pragma unroll
    for (int mt = 0; mt < 2; ++mt)
        aoff[mt] = (uint32_t)((wm * 32 + mt * 16 + (sel & 1) * 8 + lr) * AH_STR +
                              (sel >> 1) * 8);
    const uint32_t lm_half = (uint32_t)((lane & 15) * BH_STR + wn * 64 + ((lane >> 4) << 3));

    float ra[2][4];
    float acc[2][8][4];
    #pragma unroll
    for (int i = 0; i < 2; i++)
        #pragma unroll
        for (int j = 0; j < 8; j++)
            #pragma unroll
            for (int r = 0; r < 4; r++) acc[i][j][r] = 0.0f;

    auto ldA = [&](int k0) {
        #pragma unroll
        for (int it = 0; it < 2; ++it) {
            const float* p = Ag + (size_t)(k0 + it * 16 + ar4) * NSEQ + j0 + am;
            ra[it][0] = p[0]; ra[it][1] = p[NSEQ];
            ra[it][2] = p[2 * NSEQ]; ra[it][3] = p[3 * NSEQ];
        }
    };
    auto stA = [&](int buf) {
        __half* base = Ah + buf * AH_BUF + am * AH_STR;
        #pragma unroll
        for (int it = 0; it < 2; ++it) {
            __half2 h01 = __floats2half2_rn(__expf(-coef * ra[it][0]),
                                            __expf(-coef * ra[it][1]));
            __half2 h23 = __floats2half2_rn(__expf(-coef * ra[it][2]),
                                            __expf(-coef * ra[it][3]));
            uint2 u;
            u.x = *reinterpret_cast<uint32_t*>(&h01);
            u.y = *reinterpret_cast<uint32_t*>(&h23);
            *reinterpret_cast<uint2*>(base + it * 16 + ar4) = u;
        }
    };
    auto cpB = [&](int stage, int k0) {
        #pragma unroll
        for (int it = 0; it < 2; ++it) {
            int ch = tid + it * 512;
            int row = ch >> 5, cc = (ch & 31) << 3;
            cp16(Bh + stage * BH_BUF + row * BH_STR + cc,
                 Xg + (size_t)(k0 + row) * 256 + cc);
        }
    };

    cpB(0, 0);  cp_commit();
    cpB(1, 32); cp_commit();
    ldA(0);
    stA(0);
    cp_wait1();
    __syncthreads();

    for (int kt = 0; kt < 128; ++kt) {
        const int sbuf = kt % 3;
        const int abuf = kt & 1;
        if (kt + 2 < 128) { cpB((kt + 2) % 3, (kt + 2) * 32); cp_commit(); }
        if (kt + 1 < 128) ldA((kt + 1) * 32);

        const uint32_t abase = smb + 2u * (abuf * AH_BUF);
        const uint32_t bbase = smb + 2u * (BH_OFF + sbuf * BH_BUF + lm_half);
        #pragma unroll
        for (int ks = 0; ks < 2; ++ks) {
            const int kb = ks * 16;
            uint32_t a[2][4];
            #pragma unroll
            for (int mt = 0; mt < 2; ++mt)
                ldmx4(a[mt][0], a[mt][1], a[mt][2], a[mt][3],
                      abase + 2u * (aoff[mt] + kb));
            #pragma unroll
            for (int np = 0; np < 4; ++np) {
                uint32_t r0, r1, r2, r3;
                ldmx4t(r0, r1, r2, r3, bbase + 2u * (kb * BH_STR + np * 16));
                uint32_t b0[2] = {r0, r1}, b1[2] = {r2, r3};
                mma_f16(acc[0][np * 2],     a[0], b0);
                mma_f16(acc[1][np * 2],     a[1], b0);
                mma_f16(acc[0][np * 2 + 1], a[0], b1);
                mma_f16(acc[1][np * 2 + 1], a[1], b1);
            }
        }
        if (kt + 1 < 128) stA(abuf ^ 1);
        cp_wait1();
        __syncthreads();
    }

    const size_t rowbase = (size_t)b * NSEQ + j0;
    #pragma unroll
    for (int mt = 0; mt < 2; ++mt) {
        const int r0 = wm * 32 + mt * 16 + g;
        #pragma unroll
        for (int nt = 0; nt < 8; ++nt) {
            const int e = wn * 32 + nt * 4 + tg;
            const size_t i0 = (rowbase + r0) * 128 + e;
            const size_t i1 = (rowbase + r0 + 8) * 128 + e;
            g_att[i0] = g_S[i0] * __fdividef(acc[mt][nt][0], acc[mt][nt][1]);
            g_att[i1] = g_S[i1] * __fdividef(acc[mt][nt][2], acc[mt][nt][3]);
        }
    }
}

// ---------------------------------------------------------------------------
// Small GEMM v2: BM=64, BN=128, 256 threads (8 warps, 2m x 4n of 32x32).
// mode 2: relu(+bias)   mode 3: +bias+res
// ---------------------------------------------------------------------------
__global__ __launch_bounds__(256)
void gemm64_kernel(const float* __restrict__ A, const float* __restrict__ B,
                   float* __restrict__ C, int K, int N, int mode,
                   const float* __restrict__ bias, const float* __restrict__ res) {
    __shared__ float As[64 * 36];
    __shared__ float Bs[32 * 132];
    const int m0 = blockIdx.x * 64;
    const int n0 = blockIdx.y * 128;
    const int tid = threadIdx.x, lane = tid & 31, warp = tid >> 5;
    const int wm = warp >> 2, wn = warp & 3;   // 2m x 4n
    const int g = lane >> 2, tg = lane & 3;

    float acc[2][4][4];
    #pragma unroll
    for (int i = 0; i < 2; i++)
        #pragma unroll
        for (int j = 0; j < 4; j++)
            #pragma unroll
            for (int r = 0; r < 4; r++) acc[i][j][r] = 0.0f;

    for (int k0 = 0; k0 < K; k0 += 32) {
        #pragma unroll
        for (int i = 0; i < 2; i++) {
            int id = tid + i * 256;
            int m = id >> 3, c = (id & 7) << 2;
            float4 v = *reinterpret_cast<const float4*>(A + (size_t)(m0 + m) * K + k0 + c);
            float* p = As + m * 36 + c;
            p[0] = tf32r(v.x); p[1] = tf32r(v.y); p[2] = tf32r(v.z); p[3] = tf32r(v.w);
        }
        #pragma unroll
        for (int i = 0; i < 4; i++) {
            int id = tid + i * 256;
            int k = id >> 5, c = (id & 31) << 2;
            float4 v = *reinterpret_cast<const float4*>(B + (size_t)(k0 + k) * N + n0 + c);
            float* p = Bs + k * 132 + c;
            p[0] = tf32r(v.x); p[1] = tf32r(v.y); p[2] = tf32r(v.z); p[3] = tf32r(v.w);
        }
        __syncthreads();
        #pragma unroll
        for (int ks = 0; ks < 4; ++ks) {
            const int kr = ks * 8 + tg;
            float a[2][4];
            #pragma unroll
            for (int mt = 0; mt < 2; ++mt) {
                int m = wm * 32 + mt * 16 + g;
                a[mt][0] = As[m * 36 + kr];
                a[mt][1] = As[(m + 8) * 36 + kr];
                a[mt][2] = As[m * 36 + kr + 4];
                a[mt][3] = As[(m + 8) * 36 + kr + 4];
            }
            #pragma unroll
            for (int nt = 0; nt < 4; ++nt) {
                int n = wn * 32 + nt * 8 + g;
                float bb[2];
                bb[0] = Bs[kr * 132 + n];
                bb[1] = Bs[(kr + 4) * 132 + n];
                mma_tf32(acc[0][nt], a[0], bb);
                mma_tf32(acc[1][nt], a[1], bb);
            }
        }
        __syncthreads();
    }

    #pragma unroll
    for (int mt = 0; mt < 2; ++mt) {
        const int row0 = m0 + wm * 32 + mt * 16 + g;
        #pragma unroll
        for (int nt = 0; nt < 4; ++nt) {
            const int col = n0 + wn * 32 + nt * 8 + tg * 2;
            #pragma unroll
            for (int h = 0; h < 2; ++h) {
                const int row = row0 + h * 8;
                float v0 = acc[mt][nt][h * 2 + 0];
                float v1 = acc[mt][nt][h * 2 + 1];
                if (mode == 2) {
                    v0 = fmaxf(v0 + bias[col], 0.0f);
                    v1 = fmaxf(v1 + bias[col + 1], 0.0f);
                } else {
                    v0 += bias[col]     + res[(size_t)row * N + col];
                    v1 += bias[col + 1] + res[(size_t)row * N + col + 1];
                }
                C[(size_t)row * N + col]     = v0;
                C[(size_t)row * N + col + 1] = v1;
            }
        }
    }
}

// ---------------------------------------------------------------------------
// Wo GEMM + residual + fused post-rmsnorm.
// out1 = x + att @ Wo ; h2 = rmsnorm(out1) * g_post.  BM=64, N=K=128.
// ---------------------------------------------------------------------------
__global__ __launch_bounds__(256)
void wo_norm_kernel(const float* __restrict__ A, const float* __restrict__ B,
                    const float* __restrict__ x, const float* __restrict__ gpost,
                    float* __restrict__ out1, float* __restrict__ h2) {
    __shared__ float As[64 * 36];
    __shared__ float Bs[32 * 132];
    __shared__ float rowss[64];
    const int m0 = blockIdx.x * 64;
    const int tid = threadIdx.x, lane = tid & 31, warp = tid >> 5;
    const int wm = warp >> 2, wn = warp & 3;
    const int g = lane >> 2, tg = lane & 3;

    if (tid < 64) rowss[tid] = 0.0f;

    float acc[2][4][4];
    #pragma unroll
    for (int i = 0; i < 2; i++)
        #pragma unroll
        for (int j = 0; j < 4; j++)
            #pragma unroll
            for (int r = 0; r < 4; r++) acc[i][j][r] = 0.0f;

    for (int k0 = 0; k0 < 128; k0 += 32) {
        #pragma unroll
        for (int i = 0; i < 2; i++) {
            int id = tid + i * 256;
            int m = id >> 3, c = (id & 7) << 2;
            float4 v = *reinterpret_cast<const float4*>(A + (size_t)(m0 + m) * 128 + k0 + c);
            float* p = As + m * 36 + c;
            p[0] = tf32r(v.x); p[1] = tf32r(v.y); p[2] = tf32r(v.z); p[3] = tf32r(v.w);
        }
        #pragma unroll
        for (int i = 0; i < 4; i++) {
            int id = tid + i * 256;
            int k = id >> 5, c = (id & 31) << 2;
            float4 v = *reinterpret_cast<const float4*>(B + (size_t)(k0 + k) * 128 + c);
            float* p = Bs + k * 132 + c;
            p[0] = tf32r(v.x); p[1] = tf32r(v.y); p[2] = tf32r(v.z); p[3] = tf32r(v.w);
        }
        __syncthreads();
        #pragma unroll
        for (int ks = 0; ks < 4; ++ks) {
            const int kr = ks * 8 + tg;
            float a[2][4];
            #pragma unroll
            for (int mt = 0; mt < 2; ++mt) {
                int m = wm * 32 + mt * 16 + g;
                a[mt][0] = As[m * 36 + kr];
                a[mt][1] = As[(m + 8) * 36 + kr];
                a[mt][2] = As[m * 36 + kr + 4];
                a[mt][3] = As[(m + 8) * 36 + kr + 4];
            }
            #pragma unroll
            for (int nt = 0; nt < 4; ++nt) {
                int n = wn * 32 + nt * 8 + g;
                float bb[2];
                bb[0] = Bs[kr * 132 + n];
                bb[1] = Bs[(kr + 4) * 132 + n];
                mma_tf32(acc[0][nt], a[0], bb);
                mma_tf32(acc[1][nt], a[1], bb);
            }
        }
        __syncthreads();
    }

    // add residual, store out1, accumulate row sum-of-squares
    #pragma unroll
    for (int mt = 0; mt < 2; ++mt) {
        #pragma unroll
        for (int h = 0; h < 2; ++h) {
            const int rl = wm * 32 + mt * 16 + g + h * 8;
            const int row = m0 + rl;
            float ss = 0.0f;
            #pragma unroll
            for (int nt = 0; nt < 4; ++nt) {
                const int col = wn * 32 + nt * 8 + tg * 2;
                float v0 = acc[mt][nt][h * 2 + 0] + x[(size_t)row * 128 + col];
                float v1 = acc[mt][nt][h * 2 + 1] + x[(size_t)row * 128 + col + 1];
                acc[mt][nt][h * 2 + 0] = v0;
                acc[mt][nt][h * 2 + 1] = v1;
                out1[(size_t)row * 128 + col]     = v0;
                out1[(size_t)row * 128 + col + 1] = v1;
                ss += v0 * v0 + v1 * v1;
            }
            atomicAdd(&rowss[rl], ss);
        }
    }
    __syncthreads();

    // h2 = out1 * rsqrt(mean+eps) * g_post
    #pragma unroll
    for (int mt = 0; mt < 2; ++mt) {
        #pragma unroll
        for (int h = 0; h < 2; ++h) {
            const int rl = wm * 32 + mt * 16 + g + h * 8;
            const int row = m0 + rl;
            const float s = rsqrtf(rowss[rl] * (1.0f / 128.0f) + 1e-6f);
            #pragma unroll
            for (int nt = 0; nt < 4; ++nt) {
                const int col = wn * 32 + nt * 8 + tg * 2;
                h2[(size_t)row * 128 + col]     = acc[mt][nt][h * 2 + 0] * s * gpost[col];
                h2[(size_t)row * 128 + col + 1] = acc[mt][nt][h * 2 + 1] * s * gpost[col + 1];
            }
        }
    }
}

// ---------------- launch ----------------
extern "C" void kernel_launch(void* const* d_in, const int* in_sizes, int n_in,
                              void* d_out, int out_size) {
    const float* x     = (const float*)d_in[0];
    const float* dis   = (const float*)d_in[1];
    const float* g_in  = (const float*)d_in[2];
    const float* g_po  = (const float*)d_in[3];
    const float* Wq    = (const float*)d_in[4];
    const float* Wk    = (const float*)d_in[5];
    const float* Wv    = (const float*)d_in[6];
    const float* alpha = (const float*)d_in[7];
    const float* Wo    = (const float*)d_in[8];
    const float* W1    = (const float*)d_in[9];
    const float* b1    = (const float*)d_in[10];
    const float* W2    = (const float*)d_in[11];
    const float* b2    = (const float*)d_in[12];
    float* out = (float*)d_out;

    float *p_h, *p_att, *p_out1, *p_h2, *p_t;
    cudaGetSymbolAddress((void**)&p_h,    g_h);
    cudaGetSymbolAddress((void**)&p_att,  g_att);
    cudaGetSymbolAddress((void**)&p_out1, g_out1);
    cudaGetSymbolAddress((void**)&p_h2,   g_h2);
    cudaGetSymbolAddress((void**)&p_t,    g_t);

    cudaFuncSetAttribute(big_kernel,
                         cudaFuncAttributeMaxDynamicSharedMemorySize, BIG_SMEM);

    rmsnorm_kernel<<<NTOK / 8, 256>>>(x, g_in, p_h);
    qkv_kernel<<<dim3(NTOK / 128, 4), 256>>>(p_h, Wq, Wk, Wv);
    big_kernel<<<dim3(NSEQ / 128, NB), 512, BIG_SMEM>>>(dis, alpha);
    // out1 = x + att @ Wo ; h2 = rmsnorm(out1) * g_post  (fused)
    wo_norm_kernel<<<NTOK / 64, 256>>>(p_att, Wo, x, g_po, p_out1, p_h2);
    // t = relu(h2 @ W1 + b1)
    gemm64_kernel<<<dim3(NTOK / 64, 4), 256>>>(p_h2, W1, p_t,
                                               128, 512, 2, b1, nullptr);
    // out = out1 + t @ W2 + b2
    gemm64_kernel<<<dim3(NTOK / 64, 1), 256>>>(p_t, W2, out,
                                               512, 128, 3, b2, p_out1);
}

// round 8
// speedup vs baseline: 1.0736x; 1.0736x over previous
#include <cuda_runtime.h>
#include <cuda_fp16.h>
#include <cstdint>
#include <cstddef>

#define NB     4
#define NSEQ   4096
#define EDIM   128
#define FFD    512
#define NTOK   (NB * NSEQ)

// ---------------- scratch ----------------
__device__ float  g_h   [NTOK * EDIM];
__device__ float  g_S   [NTOK * EDIM];
__device__ __half g_Xh  [NTOK * 256];     // [t][256]: 2e=exp(k)*v, 2e+1=exp(k)
__device__ float  g_att [NTOK * EDIM];
__device__ float  g_out1[NTOK * EDIM];
__device__ float  g_h2  [NTOK * EDIM];
__device__ float  g_t   [NTOK * FFD];

// ---------------- helpers ----------------
__device__ __forceinline__ float tf32r(float x) {
    uint32_t u;
    asm("cvt.rna.tf32.f32 %0, %1;" : "=r"(u) : "f"(x));
    return __uint_as_float(u);
}
__device__ __forceinline__ void mma_tf32(float* c, const float* a, const float* b) {
    asm volatile(
        "mma.sync.aligned.m16n8k8.row.col.f32.tf32.tf32.f32 "
        "{%0,%1,%2,%3}, {%4,%5,%6,%7}, {%8,%9}, {%0,%1,%2,%3};\n"
        : "+f"(c[0]), "+f"(c[1]), "+f"(c[2]), "+f"(c[3])
        : "r"(__float_as_uint(a[0])), "r"(__float_as_uint(a[1])),
          "r"(__float_as_uint(a[2])), "r"(__float_as_uint(a[3])),
          "r"(__float_as_uint(b[0])), "r"(__float_as_uint(b[1])));
}
__device__ __forceinline__ void mma_f16(float* c, const uint32_t* a, const uint32_t* b) {
    asm volatile(
        "mma.sync.aligned.m16n8k16.row.col.f32.f16.f16.f32 "
        "{%0,%1,%2,%3}, {%4,%5,%6,%7}, {%8,%9}, {%0,%1,%2,%3};\n"
        : "+f"(c[0]), "+f"(c[1]), "+f"(c[2]), "+f"(c[3])
        : "r"(a[0]), "r"(a[1]), "r"(a[2]), "r"(a[3]), "r"(b[0]), "r"(b[1]));
}
__device__ __forceinline__ void cp16(void* s, const void* gp) {
    uint32_t sa = (uint32_t)__cvta_generic_to_shared(s);
    asm volatile("cp.async.cg.shared.global [%0], [%1], 16;\n" :: "r"(sa), "l"(gp));
}
__device__ __forceinline__ void cp_commit() {
    asm volatile("cp.async.commit_group;\n" ::: "memory");
}
__device__ __forceinline__ void cp_wait0() {
    asm volatile("cp.async.wait_group 0;\n" ::: "memory");
}
__device__ __forceinline__ void cp_wait1() {
    asm volatile("cp.async.wait_group 1;\n" ::: "memory");
}
__device__ __forceinline__ void ldmx4(uint32_t& r0, uint32_t& r1, uint32_t& r2,
                                      uint32_t& r3, uint32_t addr) {
    asm volatile("ldmatrix.sync.aligned.m8n8.x4.shared.b16 {%0,%1,%2,%3}, [%4];"
                 : "=r"(r0), "=r"(r1), "=r"(r2), "=r"(r3) : "r"(addr));
}
__device__ __forceinline__ void ldmx4t(uint32_t& r0, uint32_t& r1, uint32_t& r2,
                                       uint32_t& r3, uint32_t addr) {
    asm volatile("ldmatrix.sync.aligned.m8n8.x4.trans.shared.b16 {%0,%1,%2,%3}, [%4];"
                 : "=r"(r0), "=r"(r1), "=r"(r2), "=r"(r3) : "r"(addr));
}
__device__ __forceinline__ uint32_t smem_u32(const void* p) {
    return (uint32_t)__cvta_generic_to_shared(p);
}

// ---------------- rmsnorm ----------------
__global__ void rmsnorm_kernel(const float* __restrict__ x,
                               const float* __restrict__ gw,
                               float* __restrict__ y) {
    int warp = (blockIdx.x * blockDim.x + threadIdx.x) >> 5;
    int lane = threadIdx.x & 31;
    if (warp >= NTOK) return;
    float4 v = reinterpret_cast<const float4*>(x + (size_t)warp * EDIM)[lane];
    float ss = v.x * v.x + v.y * v.y + v.z * v.z + v.w * v.w;
    #pragma unroll
    for (int o = 16; o > 0; o >>= 1) ss += __shfl_xor_sync(0xffffffffu, ss, o);
    float s = rsqrtf(ss * (1.0f / 128.0f) + 1e-6f);
    float4 g4 = reinterpret_cast<const float4*>(gw)[lane];
    float4 o4 = make_float4(v.x * s * g4.x, v.y * s * g4.y, v.z * s * g4.z, v.w * s * g4.w);
    reinterpret_cast<float4*>(y + (size_t)warp * EDIM)[lane] = o4;
}

// ---------------------------------------------------------------------------
// Fused QKV GEMM (cp.async double-buffered): block = 128 tokens x 32 cols of
// q,k,v. Epilogue: g_S = sigmoid(q); g_Xh = interleaved half pairs.
// Dynamic smem: 2 x (128*36 + 3*32*36) floats = 64512 bytes.
// ---------------------------------------------------------------------------
#define QK_A   4608               // 128*36 floats
#define QK_B   1152               // 32*36 floats (per weight)
#define QK_BUF (QK_A + 3 * QK_B)  // 8064 floats
#define QKV_SMEM (2 * QK_BUF * 4) // 64512 bytes

__global__ __launch_bounds__(256)
void qkv_kernel(const float* __restrict__ h, const float* __restrict__ Wq,
                const float* __restrict__ Wk, const float* __restrict__ Wv) {
    extern __shared__ float smq[];
    const int m0 = blockIdx.x * 128;
    const int j0 = blockIdx.y * 32;
    const int tid = threadIdx.x, lane = tid & 31, warp = tid >> 5;
    const int wm = warp >> 1, wn = warp & 1;    // 4 x 2 warps, 32m x 16n each
    const int g = lane >> 2, tg = lane & 3;

    const float* Wp[3] = {Wq, Wk, Wv};

    auto cpTile = [&](int buf, int k0) {
        float* As = smq + buf * QK_BUF;
        #pragma unroll
        for (int i = 0; i < 4; i++) {
            int id = tid + i * 256;
            int m = id >> 3, c = (id & 7) << 2;
            cp16(As + m * 36 + c, h + (size_t)(m0 + m) * 128 + k0 + c);
        }
        int k = tid >> 3, c = (tid & 7) << 2;
        #pragma unroll
        for (int w = 0; w < 3; w++)
            cp16(As + QK_A + w * QK_B + k * 36 + c,
                 Wp[w] + (size_t)(k0 + k) * 128 + j0 + c);
    };

    float acc[3][2][2][4];
    #pragma unroll
    for (int w = 0; w < 3; w++)
        #pragma unroll
        for (int i = 0; i < 2; i++)
            #pragma unroll
            for (int j = 0; j < 2; j++)
                #pragma unroll
                for (int r = 0; r < 4; r++) acc[w][i][j][r] = 0.0f;

    cpTile(0, 0);
    cp_commit();

    for (int kt = 0; kt < 4; ++kt) {
        const int buf = kt & 1;
        if (kt + 1 < 4) { cpTile(buf ^ 1, (kt + 1) * 32); cp_commit(); cp_wait1(); }
        else            { cp_wait0(); }
        __syncthreads();
        const float* As = smq + buf * QK_BUF;
        const float* Bs = As + QK_A;
        #pragma unroll
        for (int ks = 0; ks < 4; ++ks) {
            const int kr = ks * 8 + tg;
            float a[2][4];
            #pragma unroll
            for (int mt = 0; mt < 2; ++mt) {
                int m = wm * 32 + mt * 16 + g;
                a[mt][0] = tf32r(As[m * 36 + kr]);
                a[mt][1] = tf32r(As[(m + 8) * 36 + kr]);
                a[mt][2] = tf32r(As[m * 36 + kr + 4]);
                a[mt][3] = tf32r(As[(m + 8) * 36 + kr + 4]);
            }
            #pragma unroll
            for (int w = 0; w < 3; w++) {
                #pragma unroll
                for (int nt = 0; nt < 2; ++nt) {
                    int n = wn * 16 + nt * 8 + g;
                    float bb[2];
                    bb[0] = tf32r(Bs[w * QK_B + kr * 36 + n]);
                    bb[1] = tf32r(Bs[w * QK_B + (kr + 4) * 36 + n]);
                    mma_tf32(acc[w][0][nt], a[0], bb);
                    mma_tf32(acc[w][1][nt], a[1], bb);
                }
            }
        }
        __syncthreads();
    }

    // epilogue
    #pragma unroll
    for (int mt = 0; mt < 2; ++mt) {
        #pragma unroll
        for (int nt = 0; nt < 2; ++nt) {
            const int col = j0 + wn * 16 + nt * 8 + tg * 2;
            #pragma unroll
            for (int hh = 0; hh < 2; ++hh) {
                const int row = m0 + wm * 32 + mt * 16 + g + hh * 8;
                float q0 = acc[0][mt][nt][hh * 2], q1 = acc[0][mt][nt][hh * 2 + 1];
                float k0v = acc[1][mt][nt][hh * 2], k1v = acc[1][mt][nt][hh * 2 + 1];
                float v0 = acc[2][mt][nt][hh * 2], v1 = acc[2][mt][nt][hh * 2 + 1];
                float2 s2 = make_float2(1.0f / (1.0f + expf(-q0)),
                                        1.0f / (1.0f + expf(-q1)));
                *reinterpret_cast<float2*>(g_S + (size_t)row * 128 + col) = s2;
                float kw0 = expf(k0v), kw1 = expf(k1v);
                __half2 h0 = __floats2half2_rn(kw0 * v0, kw0);
                __half2 h1 = __floats2half2_rn(kw1 * v1, kw1);
                uint2 u;
                u.x = *reinterpret_cast<uint32_t*>(&h0);
                u.y = *reinterpret_cast<uint32_t*>(&h1);
                *reinterpret_cast<uint2*>(g_Xh + (size_t)row * 256 + 2 * col) = u;
            }
        }
    }
}

// ---------------------------------------------------------------------------
// Big GEMM (fp16 m16n8k16), per batch: D[j,n] = sum_i exp(-coef*dis[i,j])*Xh[i,n]
// (unchanged from R6 — measured near its HMMA floor)
// ---------------------------------------------------------------------------
#define AH_STR 40
#define AH_BUF 5120
#define BH_STR 264
#define BH_BUF 8448
#define BH_OFF 10240
#define BIG_SMEM 71168

__global__ __launch_bounds__(512, 1)
void big_kernel(const float* __restrict__ dis, const float* __restrict__ alphap) {
    extern __shared__ __half smh[];
    __half* Ah = smh;
    __half* Bh = smh + BH_OFF;
    const uint32_t smb = smem_u32(smh);

    const int tid = threadIdx.x, lane = tid & 31, warp = tid >> 5;
    const int wm = warp >> 2, wn = warp & 3;
    const int g = lane >> 2, tg = lane & 3;
    const int b = blockIdx.y, j0 = blockIdx.x * 128;
    const float coef = 12.0f * alphap[0];
    const float* Ag = dis + (size_t)b * NSEQ * NSEQ;
    const __half* Xg = g_Xh + (size_t)b * NSEQ * 256;

    const int am = tid & 127, ar4 = (tid >> 7) << 2;

    const int lr = lane & 7, sel = lane >> 3;
    uint32_t aoff[2];
    #pragma unroll
    for (int mt = 0; mt < 2; ++mt)
        aoff[mt] = (uint32_t)((wm * 32 + mt * 16 + (sel & 1) * 8 + lr) * AH_STR +
                              (sel >> 1) * 8);
    const uint32_t lm_half = (uint32_t)((lane & 15) * BH_STR + wn * 64 + ((lane >> 4) << 3));

    float ra[2][4];
    float acc[2][8][4];
    #pragma unroll
    for (int i = 0; i < 2; i++)
        #pragma unroll
        for (int j = 0; j < 8; j++)
            #pragma unroll
            for (int r = 0; r < 4; r++) acc[i][j][r] = 0.0f;

    auto ldA = [&](int k0) {
        #pragma unroll
        for (int it = 0; it < 2; ++it) {
            const float* p = Ag + (size_t)(k0 + it * 16 + ar4) * NSEQ + j0 + am;
            ra[it][0] = p[0]; ra[it][1] = p[NSEQ];
            ra[it][2] = p[2 * NSEQ]; ra[it][3] = p[3 * NSEQ];
        }
    };
    auto stA = [&](int buf) {
        __half* base = Ah + buf * AH_BUF + am * AH_STR;
        #pragma unroll
        for (int it = 0; it < 2; ++it) {
            __half2 h01 = __floats2half2_rn(__expf(-coef * ra[it][0]),
                                            __expf(-coef * ra[it][1]));
            __half2 h23 = __floats2half2_rn(__expf(-coef * ra[it][2]),
                                            __expf(-coef * ra[it][3]));
            uint2 u;
            u.x = *reinterpret_cast<uint32_t*>(&h01);
            u.y = *reinterpret_cast<uint32_t*>(&h23);
            *reinterpret_cast<uint2*>(base + it * 16 + ar4) = u;
        }
    };
    auto cpB = [&](int stage, int k0) {
        #pragma unroll
        for (int it = 0; it < 2; ++it) {
            int ch = tid + it * 512;
            int row = ch >> 5, cc = (ch & 31) << 3;
            cp16(Bh + stage * BH_BUF + row * BH_STR + cc,
                 Xg + (size_t)(k0 + row) * 256 + cc);
        }
    };

    cpB(0, 0);  cp_commit();
    cpB(1, 32); cp_commit();
    ldA(0);
    stA(0);
    cp_wait1();
    __syncthreads();

    for (int kt = 0; kt < 128; ++kt) {
        const int sbuf = kt % 3;
        const int abuf = kt & 1;
        if (kt + 2 < 128) { cpB((kt + 2) % 3, (kt + 2) * 32); cp_commit(); }
        if (kt + 1 < 128) ldA((kt + 1) * 32);

        const uint32_t abase = smb + 2u * (abuf * AH_BUF);
        const uint32_t bbase = smb + 2u * (BH_OFF + sbuf * BH_BUF + lm_half);
        #pragma unroll
        for (int ks = 0; ks < 2; ++ks) {
            const int kb = ks * 16;
            uint32_t a[2][4];
            #pragma unroll
            for (int mt = 0; mt < 2; ++mt)
                ldmx4(a[mt][0], a[mt][1], a[mt][2], a[mt][3],
                      abase + 2u * (aoff[mt] + kb));
            #pragma unroll
            for (int np = 0; np < 4; ++np) {
                uint32_t r0, r1, r2, r3;
                ldmx4t(r0, r1, r2, r3, bbase + 2u * (kb * BH_STR + np * 16));
                uint32_t b0[2] = {r0, r1}, b1[2] = {r2, r3};
                mma_f16(acc[0][np * 2],     a[0], b0);
                mma_f16(acc[1][np * 2],     a[1], b0);
                mma_f16(acc[0][np * 2 + 1], a[0], b1);
                mma_f16(acc[1][np * 2 + 1], a[1], b1);
            }
        }
        if (kt + 1 < 128) stA(abuf ^ 1);
        cp_wait1();
        __syncthreads();
    }

    const size_t rowbase = (size_t)b * NSEQ + j0;
    #pragma unroll
    for (int mt = 0; mt < 2; ++mt) {
        const int r0 = wm * 32 + mt * 16 + g;
        #pragma unroll
        for (int nt = 0; nt < 8; ++nt) {
            const int e = wn * 32 + nt * 4 + tg;
            const size_t i0 = (rowbase + r0) * 128 + e;
            const size_t i1 = (rowbase + r0 + 8) * 128 + e;
            g_att[i0] = g_S[i0] * __fdividef(acc[mt][nt][0], acc[mt][nt][1]);
            g_att[i1] = g_S[i1] * __fdividef(acc[mt][nt][2], acc[mt][nt][3]);
        }
    }
}

// ---------------------------------------------------------------------------
// Small GEMM (tf32, cp.async double-buffered): BM=128, BN=64, 256 threads.
// mode 1: +res   2: relu(+bias)   3: +bias+res
// Dynamic smem: 2 x (128*36 + 32*72) floats = 55296 bytes.
// ---------------------------------------------------------------------------
#define SG_A   4608              // 128*36
#define SG_B   2304              // 32*72
#define SG_BUF (SG_A + SG_B)     // 6912 floats
#define SG_SMEM (2 * SG_BUF * 4) // 55296 bytes

__global__ __launch_bounds__(256)
void gemm_small_kernel(const float* __restrict__ A, const float* __restrict__ B,
                       float* __restrict__ C, int K, int N, int mode,
                       const float* __restrict__ bias, const float* __restrict__ res) {
    extern __shared__ float smg[];
    const int m0 = blockIdx.x * 128;
    const int n0 = blockIdx.y * 64;
    const int tid = threadIdx.x, lane = tid & 31, warp = tid >> 5;
    const int wm = warp >> 1, wn = warp & 1;
    const int g = lane >> 2, tg = lane & 3;

    auto cpTile = [&](int buf, int k0) {
        float* As = smg + buf * SG_BUF;
        float* Bs = As + SG_A;
        #pragma unroll
        for (int i = 0; i < 4; i++) {
            int id = tid + i * 256;
            int m = id >> 3, c = (id & 7) << 2;
            cp16(As + m * 36 + c, A + (size_t)(m0 + m) * K + k0 + c);
        }
        #pragma unroll
        for (int i = 0; i < 2; i++) {
            int id = tid + i * 256;
            int k = id >> 4, c = (id & 15) << 2;
            cp16(Bs + k * 72 + c, B + (size_t)(k0 + k) * N + n0 + c);
        }
    };

    float acc[2][4][4];
    #pragma unroll
    for (int i = 0; i < 2; i++)
        #pragma unroll
        for (int j = 0; j < 4; j++)
            #pragma unroll
            for (int r = 0; r < 4; r++) acc[i][j][r] = 0.0f;

    const int KT = K / 32;
    cpTile(0, 0);
    cp_commit();

    for (int kt = 0; kt < KT; ++kt) {
        const int buf = kt & 1;
        if (kt + 1 < KT) { cpTile(buf ^ 1, (kt + 1) * 32); cp_commit(); cp_wait1(); }
        else             { cp_wait0(); }
        __syncthreads();
        const float* As = smg + buf * SG_BUF;
        const float* Bs = As + SG_A;
        #pragma unroll
        for (int ks = 0; ks < 4; ++ks) {
            const int kr = ks * 8 + tg;
            float a[2][4];
            #pragma unroll
            for (int mt = 0; mt < 2; ++mt) {
                int m = wm * 32 + mt * 16 + g;
                a[mt][0] = tf32r(As[m * 36 + kr]);
                a[mt][1] = tf32r(As[(m + 8) * 36 + kr]);
                a[mt][2] = tf32r(As[m * 36 + kr + 4]);
                a[mt][3] = tf32r(As[(m + 8) * 36 + kr + 4]);
            }
            float bb[4][2];
            #pragma unroll
            for (int nt = 0; nt < 4; ++nt) {
                int n = wn * 32 + nt * 8 + g;
                bb[nt][0] = tf32r(Bs[kr * 72 + n]);
                bb[nt][1] = tf32r(Bs[(kr + 4) * 72 + n]);
            }
            #pragma unroll
            for (int mt = 0; mt < 2; ++mt)
                #pragma unroll
                for (int nt = 0; nt < 4; ++nt)
                    mma_tf32(acc[mt][nt], a[mt], bb[nt]);
        }
        __syncthreads();
    }

    #pragma unroll
    for (int mt = 0; mt < 2; ++mt) {
        const int row0 = m0 + wm * 32 + mt * 16 + g;
        #pragma unroll
        for (int nt = 0; nt < 4; ++nt) {
            const int col = n0 + wn * 32 + nt * 8 + tg * 2;
            #pragma unroll
            for (int h = 0; h < 2; ++h) {
                const int row = row0 + h * 8;
                float v0 = acc[mt][nt][h * 2 + 0];
                float v1 = acc[mt][nt][h * 2 + 1];
                if (mode == 1) {
                    v0 += res[(size_t)row * N + col];
                    v1 += res[(size_t)row * N + col + 1];
                } else if (mode == 2) {
                    v0 = fmaxf(v0 + bias[col], 0.0f);
                    v1 = fmaxf(v1 + bias[col + 1], 0.0f);
                } else if (mode == 3) {
                    v0 += bias[col]     + res[(size_t)row * N + col];
                    v1 += bias[col + 1] + res[(size_t)row * N + col + 1];
                }
                C[(size_t)row * N + col]     = v0;
                C[(size_t)row * N + col + 1] = v1;
            }
        }
    }
}

// ---------------- launch ----------------
extern "C" void kernel_launch(void* const* d_in, const int* in_sizes, int n_in,
                              void* d_out, int out_size) {
    const float* x     = (const float*)d_in[0];
    const float* dis   = (const float*)d_in[1];
    const float* g_in  = (const float*)d_in[2];
    const float* g_po  = (const float*)d_in[3];
    const float* Wq    = (const float*)d_in[4];
    const float* Wk    = (const float*)d_in[5];
    const float* Wv    = (const float*)d_in[6];
    const float* alpha = (const float*)d_in[7];
    const float* Wo    = (const float*)d_in[8];
    const float* W1    = (const float*)d_in[9];
    const float* b1    = (const float*)d_in[10];
    const float* W2    = (const float*)d_in[11];
    const float* b2    = (const float*)d_in[12];
    float* out = (float*)d_out;

    float *p_h, *p_att, *p_out1, *p_h2, *p_t;
    cudaGetSymbolAddress((void**)&p_h,    g_h);
    cudaGetSymbolAddress((void**)&p_att,  g_att);
    cudaGetSymbolAddress((void**)&p_out1, g_out1);
    cudaGetSymbolAddress((void**)&p_h2,   g_h2);
    cudaGetSymbolAddress((void**)&p_t,    g_t);

    cudaFuncSetAttribute(big_kernel,
                         cudaFuncAttributeMaxDynamicSharedMemorySize, BIG_SMEM);
    cudaFuncSetAttribute(qkv_kernel,
                         cudaFuncAttributeMaxDynamicSharedMemorySize, QKV_SMEM);
    cudaFuncSetAttribute(gemm_small_kernel,
                         cudaFuncAttributeMaxDynamicSharedMemorySize, SG_SMEM);

    rmsnorm_kernel<<<NTOK / 8, 256>>>(x, g_in, p_h);
    qkv_kernel<<<dim3(NTOK / 128, 4), 256, QKV_SMEM>>>(p_h, Wq, Wk, Wv);
    big_kernel<<<dim3(NSEQ / 128, NB), 512, BIG_SMEM>>>(dis, alpha);
    // out1 = x + att @ Wo
    gemm_small_kernel<<<dim3(NTOK / 128, 2), 256, SG_SMEM>>>(p_att, Wo, p_out1,
                                                    128, 128, 1, nullptr, x);
    rmsnorm_kernel<<<NTOK / 8, 256>>>(p_out1, g_po, p_h2);
    // t = relu(h2 @ W1 + b1)
    gemm_small_kernel<<<dim3(NTOK / 128, 8), 256, SG_SMEM>>>(p_h2, W1, p_t,
                                                    128, 512, 2, b1, nullptr);
    // out = out1 + t @ W2 + b2
    gemm_small_kernel<<<dim3(NTOK / 128, 2), 256, SG_SMEM>>>(p_t, W2, out,
                                                    512, 128, 3, b2, p_out1);
}